// round 17
// baseline (speedup 1.0000x reference)
#include <cuda_runtime.h>

namespace {

constexpr int T = 2048;
constexpr int B = 4096;
constexpr int BLK = 256;   // 64 chains/block; 64 blocks; 2 warps/SMSP on 64 SMs
constexpr int PF = 3;      // x prefetch depth per chain

typedef unsigned long long u64;

// Pure-math asm is NON-volatile: the compiler may interleave the two chains'
// independent dependency graphs — that interleaving IS the optimization.
__device__ __forceinline__ u64 pack2(float lo, float hi) {
    u64 r; asm("mov.b64 %0,{%1,%2};" : "=l"(r) : "f"(lo), "f"(hi)); return r;
}
__device__ __forceinline__ void unpack2(u64 v, float& lo, float& hi) {
    asm("mov.b64 {%0,%1},%2;" : "=f"(lo), "=f"(hi) : "l"(v));
}
__device__ __forceinline__ u64 ffma2(u64 a, u64 b, u64 c) {
    u64 d; asm("fma.rn.f32x2 %0,%1,%2,%3;" : "=l"(d) : "l"(a), "l"(b), "l"(c)); return d;
}
__device__ __forceinline__ u64 fmul2(u64 a, u64 b) {
    u64 d; asm("mul.rn.f32x2 %0,%1,%2;" : "=l"(d) : "l"(a), "l"(b)); return d;
}
__device__ __forceinline__ u64 fadd2(u64 a, u64 b) {
    u64 d; asm("add.rn.f32x2 %0,%1,%2;" : "=l"(d) : "l"(a), "l"(b)); return d;
}
__device__ __forceinline__ float tanha(float x) {
    float y; asm("tanh.approx.f32 %0,%1;" : "=f"(y) : "f"(x)); return y;
}
__device__ __forceinline__ float hadd(u64 v) {
    float lo, hi; unpack2(v, lo, hi); return lo + hi;
}
__device__ __forceinline__ unsigned smem_u32(const void* p) {
    unsigned a;
    asm("{ .reg .u64 t; cvta.to.shared.u64 t, %1; cvt.u32.u64 %0, t; }" : "=r"(a) : "l"(p));
    return a;
}

// TWO chains per thread on the 8-lane skeleton: lane l owns h_l and rows
// l (r), 8+l (z), 16+l (n) for chains cA = 2G and cB = 2G+1, sharing ONE
// register copy of all weights. The chains are independent dependency graphs;
// with non-volatile math asm the scheduler interleaves them so each chain's
// ~125-cycle loop-carried latency (STS+LDS exchange, two serial tanh) is
// hidden under the other chain's instructions — in-warp latency hiding, which
// sibling warps (R5/R8) could not provide.
// Exchange per chain: volatile STS.32 + 2 volatile LDS.128 (order pinned);
// LDS delivers h as ready-made f32x2 pairs. Gate algebra as R12/R13:
// sigma(u)=0.5+0.5*tanh(u/2) with 1/2 folded into r/z weights; n-path 0.5
// folded into Whn so the tree yields hn/2 directly.
__global__ void __launch_bounds__(BLK, 1) gru_fused_kernel(
    const float* __restrict__ x,
    const float* __restrict__ W_ih,
    const float* __restrict__ W_hh,
    const float* __restrict__ b_ih,
    const float* __restrict__ b_hh,
    const float* __restrict__ W_fc,
    const float* __restrict__ b_fc,
    float* __restrict__ out)
{
    __shared__ float hx[2 * BLK];          // 64 chains x 8 floats = 2KB

    const int l  = threadIdx.x & 7;        // lane within chain group
    const int gi = threadIdx.x >> 3;       // group within block (0..31)
    const int G  = blockIdx.x * (BLK / 8) + gi;   // global group 0..2047

    // chain A slab at [gi*64, +32), chain B slab at [gi*64+32, +32)
    const unsigned sbA = smem_u32(hx) + gi * 64;
    const unsigned sbB = sbA + 32;
    const unsigned smeA = sbA + l * 4;
    const unsigned smeB = sbB + l * 4;

    const float HS = 0.5f;

    // ---- ONE shared register copy of weights: rows l, 8+l, 16+l ----
    const int gr = l, gz = 8 + l, gn = 16 + l;
    u64 Whr[4], Whz[4], Whn[4];
#pragma unroll
    for (int k = 0; k < 4; k++) {
        Whr[k] = pack2(HS * W_hh[gr * 8 + 2 * k], HS * W_hh[gr * 8 + 2 * k + 1]);
        Whz[k] = pack2(HS * W_hh[gz * 8 + 2 * k], HS * W_hh[gz * 8 + 2 * k + 1]);
        Whn[k] = pack2(HS * W_hh[gn * 8 + 2 * k], HS * W_hh[gn * 8 + 2 * k + 1]);
    }
    u64 Wxr[2], Wxz[2], Wxn[2];
#pragma unroll
    for (int k = 0; k < 2; k++) {
        Wxr[k] = pack2(HS * W_ih[gr * 4 + 2 * k], HS * W_ih[gr * 4 + 2 * k + 1]);
        Wxz[k] = pack2(HS * W_ih[gz * 4 + 2 * k], HS * W_ih[gz * 4 + 2 * k + 1]);
        Wxn[k] = pack2(W_ih[gn * 4 + 2 * k], W_ih[gn * 4 + 2 * k + 1]);
    }
    const u64 brp   = pack2(HS * (b_ih[gr] + b_hh[gr]), 0.0f);
    const u64 bzp   = pack2(HS * (b_ih[gz] + b_hh[gz]), 0.0f);
    const u64 bxnp  = pack2(b_ih[gn], 0.0f);
    const u64 bhn2p = pack2(HS * b_hh[gn], 0.0f);

    const int o = l & 3;
    u64 Wf[4];
#pragma unroll
    for (int k = 0; k < 4; k++)
        Wf[k] = pack2(W_fc[o * 8 + 2 * k], W_fc[o * 8 + 2 * k + 1]);
    const u64 bfp = pack2(b_fc[o], 0.0f);

    // ---- per-chain state ----
    const ulonglong2* xpA = reinterpret_cast<const ulonglong2*>(x) + (size_t)(2 * G) * T;
    const ulonglong2* xpB = xpA + T;
    float* opA = out + (size_t)(2 * G) * T * 4 + o;
    float* opB = opA + (size_t)T * 4;

    u64 A01 = 0, A23 = 0, A45 = 0, A67 = 0;   // chain A h-pairs
    u64 B01 = 0, B23 = 0, B45 = 0, B67 = 0;   // chain B h-pairs
    float hA = 0.0f, hB = 0.0f;

    ulonglong2 xbA[PF], xbB[PF];
#pragma unroll
    for (int i = 0; i < PF; i++) { xbA[i] = xpA[i]; xbB[i] = xpB[i]; }

#pragma unroll 2
    for (int t = 0; t < T; t++) {
        const u64 xA0 = xbA[0].x, xA1 = xbA[0].y;
        const u64 xB0 = xbB[0].x, xB1 = xbB[0].y;
#pragma unroll
        for (int i = 0; i < PF - 1; i++) { xbA[i] = xbA[i + 1]; xbB[i] = xbB[i + 1]; }
        int tn = t + PF; tn = (tn < T) ? tn : (T - 1);
        xbA[PF - 1] = xpA[tn];
        xbB[PF - 1] = xpB[tn];

        // ---- x-side seeds, both chains ----
        u64 rA1 = ffma2(Wxr[0], xA0, brp);
        u64 rB1 = ffma2(Wxr[0], xB0, brp);
        u64 zA1 = ffma2(Wxz[0], xA0, bzp);
        u64 zB1 = ffma2(Wxz[0], xB0, bzp);
        u64 xnA = ffma2(Wxn[0], xA0, bxnp);
        u64 xnB = ffma2(Wxn[0], xB0, bxnp);
        u64 rA2 = fmul2(Wxr[1], xA1);
        u64 rB2 = fmul2(Wxr[1], xB1);
        u64 zA2 = fmul2(Wxz[1], xA1);
        u64 zB2 = fmul2(Wxz[1], xB1);
        xnA = ffma2(Wxn[1], xA1, xnA);
        xnB = ffma2(Wxn[1], xB1, xnB);

        // ---- h-side trees, chains interleaved ----
        rA1 = ffma2(Whr[0], A01, rA1);      rB1 = ffma2(Whr[0], B01, rB1);
        zA1 = ffma2(Whz[0], A01, zA1);      zB1 = ffma2(Whz[0], B01, zB1);
        u64 nA1 = ffma2(Whn[0], A01, bhn2p);
        u64 nB1 = ffma2(Whn[0], B01, bhn2p);
        rA2 = ffma2(Whr[2], A45, rA2);      rB2 = ffma2(Whr[2], B45, rB2);
        zA2 = ffma2(Whz[2], A45, zA2);      zB2 = ffma2(Whz[2], B45, zB2);
        u64 nA2 = fmul2(Whn[2], A45);
        u64 nB2 = fmul2(Whn[2], B45);
        rA1 = ffma2(Whr[1], A23, rA1);      rB1 = ffma2(Whr[1], B23, rB1);
        zA1 = ffma2(Whz[1], A23, zA1);      zB1 = ffma2(Whz[1], B23, zB1);
        nA1 = ffma2(Whn[1], A23, nA1);      nB1 = ffma2(Whn[1], B23, nB1);
        rA2 = ffma2(Whr[3], A67, rA2);      rB2 = ffma2(Whr[3], B67, rB2);
        zA2 = ffma2(Whz[3], A67, zA2);      zB2 = ffma2(Whz[3], B67, zB2);
        nA2 = ffma2(Whn[3], A67, nA2);      nB2 = ffma2(Whn[3], B67, nB2);

        // ---- activations, interleaved ----
        const float thrA = tanha(hadd(fadd2(rA1, rA2)));
        const float thrB = tanha(hadd(fadd2(rB1, rB2)));
        const float thzA = tanha(hadd(fadd2(zA1, zA2)));
        const float thzB = tanha(hadd(fadd2(zB1, zB2)));

        const float hnhA = hadd(fadd2(nA1, nA2));       // hn/2
        const float hnhB = hadd(fadd2(nB1, nB2));
        const float xnAs = hadd(xnA);
        const float xnBs = hadd(xnB);
        const float vA = fmaf(thrA, hnhA, hnhA + xnAs);
        const float vB = fmaf(thrB, hnhB, hnhB + xnBs);
        const float nA = tanha(vA);
        const float nB = tanha(vB);

        const float omzA = fmaf(-0.5f, thzA, 0.5f);
        const float omzB = fmaf(-0.5f, thzB, 0.5f);
        const float hA2 = 0.5f * hA, hB2 = 0.5f * hB;
        const float zhA = fmaf(thzA, hA2, hA2);
        const float zhB = fmaf(thzB, hB2, hB2);
        hA = fmaf(omzA, nA, zhA);
        hB = fmaf(omzB, nB, zhB);

        // ---- exchanges (order pinned within each chain) ----
        asm volatile("st.shared.f32 [%0], %1;" :: "r"(smeA), "f"(hA) : "memory");
        asm volatile("st.shared.f32 [%0], %1;" :: "r"(smeB), "f"(hB) : "memory");
        asm volatile("ld.shared.v2.b64 {%0,%1}, [%2];"
                     : "=l"(A01), "=l"(A23) : "r"(sbA) : "memory");
        asm volatile("ld.shared.v2.b64 {%0,%1}, [%2];"
                     : "=l"(A45), "=l"(A67) : "r"(sbA + 16) : "memory");
        asm volatile("ld.shared.v2.b64 {%0,%1}, [%2];"
                     : "=l"(B01), "=l"(B23) : "r"(sbB) : "memory");
        asm volatile("ld.shared.v2.b64 {%0,%1}, [%2];"
                     : "=l"(B45), "=l"(B67) : "r"(sbB + 16) : "memory");

        // ---- y_t for both chains; lanes 0-3 store ----
        u64 yaA = ffma2(Wf[0], A01, ffma2(Wf[1], A23, bfp));
        u64 yaB = ffma2(Wf[0], B01, ffma2(Wf[1], B23, bfp));
        u64 ybA = ffma2(Wf[2], A45, fmul2(Wf[3], A67));
        u64 ybB = ffma2(Wf[2], B45, fmul2(Wf[3], B67));
        const float yA = hadd(fadd2(yaA, ybA));
        const float yB = hadd(fadd2(yaB, ybB));
        if (l < 4) {
            opA[t * 4] = yA;
            opB[t * 4] = yB;
        }
    }
}

} // namespace

extern "C" void kernel_launch(void* const* d_in, const int* in_sizes, int n_in,
                              void* d_out, int out_size)
{
    const float* x    = (const float*)d_in[0];
    const float* W_ih = (const float*)d_in[1];
    const float* W_hh = (const float*)d_in[2];
    const float* b_ih = (const float*)d_in[3];
    const float* b_hh = (const float*)d_in[4];
    const float* W_fc = (const float*)d_in[5];
    const float* b_fc = (const float*)d_in[6];
    float* out = (float*)d_out;

    // 4096 chains, 2 per lane-group, 8 lanes: 16384 threads.
    // 64 blocks x 256 threads -> 8 warps/SM on 64 SMs = 2 warps/SMSP;
    // latency hiding comes from the 2 independent chains inside each thread.
    gru_fused_kernel<<<(B / 2) * 8 / BLK, BLK>>>(x, W_ih, W_hh, b_ih, b_hh, W_fc, b_fc, out);
}